// round 4
// baseline (speedup 1.0000x reference)
#include <cuda_runtime.h>

// Attention decode: out[b,:] = softmax(q[b]·K[b]^T masked) · V[b]
// B=32, S=8192, D=512, fp32. HBM-bound: ~1.07 GB/launch.

#define BB      32
#define SS      8192
#define DD      512
#define NSPLIT  16
#define ROWS_PER_BLOCK (SS / NSPLIT)    // 512
#define NWARPS  4
#define NTHREADS (NWARPS * 32)          // 128
#define NBLK    (BB * NSPLIT)           // 512

// Split-K partials (scratch; __device__ globals per allocation rules)
__device__ float g_pm[NBLK];
__device__ float g_pl[NBLK];
__device__ float g_pacc[NBLK * DD];

__global__ __launch_bounds__(NTHREADS, 4)
void attn_part1(const float* __restrict__ q,
                const float* __restrict__ k,
                const float* __restrict__ v,
                const int*   __restrict__ mask)
{
    __shared__ float s_m[NWARPS];
    __shared__ float s_l[NWARPS];
    __shared__ float s_acc[DD];

    const int b     = blockIdx.x / NSPLIT;
    const int split = blockIdx.x % NSPLIT;
    const int w     = threadIdx.x >> 5;
    const int ln    = threadIdx.x & 31;

    // zero shared accumulator
    for (int i = threadIdx.x; i < DD; i += NTHREADS) s_acc[i] = 0.0f;

    // q fragment: lane ln holds dims {4*(ln+32*j) + c}, j=0..3, c=0..3
    const float4* q4 = (const float4*)(q + (size_t)b * DD);
    float4 qf[4];
#pragma unroll
    for (int j = 0; j < 4; j++) qf[j] = q4[ln + 32 * j];

    const float4* kb = (const float4*)(k + (size_t)b * SS * DD);
    const float4* vb = (const float4*)(v + (size_t)b * SS * DD);
    const int*    mb = mask + (size_t)b * SS;

    float  m = -1e30f;
    float  l = 0.0f;
    float4 acc[4];
#pragma unroll
    for (int j = 0; j < 4; j++) acc[j] = make_float4(0.f, 0.f, 0.f, 0.f);

    const int row_base = split * ROWS_PER_BLOCK;

    // each warp handles row-pairs with warp stride
    for (int t = w; t < ROWS_PER_BLOCK / 2; t += NWARPS) {
        const int r0 = row_base + 2 * t;
        const int r1 = r0 + 1;
        const float4* k0 = kb + (size_t)r0 * (DD / 4);
        const float4* k1 = kb + (size_t)r1 * (DD / 4);
        const float4* v0 = vb + (size_t)r0 * (DD / 4);
        const float4* v1 = vb + (size_t)r1 * (DD / 4);

        // issue mask + all 16 streaming loads up front: 8 KB in flight per warp
        const int m0 = __ldg(&mb[r0]);
        const int m1 = __ldg(&mb[r1]);
        float4 ka[4], kc[4], va[4], vc[4];
#pragma unroll
        for (int j = 0; j < 4; j++) {
            ka[j] = __ldcs(&k0[ln + 32 * j]);
            kc[j] = __ldcs(&k1[ln + 32 * j]);
            va[j] = __ldcs(&v0[ln + 32 * j]);
            vc[j] = __ldcs(&v1[ln + 32 * j]);
        }

        float d0 = 0.f, d1 = 0.f;
#pragma unroll
        for (int j = 0; j < 4; j++) {
            d0 = fmaf(qf[j].x, ka[j].x, d0); d0 = fmaf(qf[j].y, ka[j].y, d0);
            d0 = fmaf(qf[j].z, ka[j].z, d0); d0 = fmaf(qf[j].w, ka[j].w, d0);
            d1 = fmaf(qf[j].x, kc[j].x, d1); d1 = fmaf(qf[j].y, kc[j].y, d1);
            d1 = fmaf(qf[j].z, kc[j].z, d1); d1 = fmaf(qf[j].w, kc[j].w, d1);
        }
        // warp butterfly reduce (all lanes end with the full dot)
#pragma unroll
        for (int o = 16; o > 0; o >>= 1) {
            d0 += __shfl_xor_sync(0xffffffffu, d0, o);
            d1 += __shfl_xor_sync(0xffffffffu, d1, o);
        }

        const float s0 = (m0 != 0) ? d0 : -1e9f;
        const float s1 = (m1 != 0) ? d1 : -1e9f;

        const float mn = fmaxf(m, fmaxf(s0, s1));
        if (mn > m) {  // warp-uniform, rare after warmup
            const float corr = __expf(m - mn);
            l *= corr;
#pragma unroll
            for (int j = 0; j < 4; j++) {
                acc[j].x *= corr; acc[j].y *= corr;
                acc[j].z *= corr; acc[j].w *= corr;
            }
            m = mn;
        }
        const float p0 = __expf(s0 - m);
        const float p1 = __expf(s1 - m);
        l += p0 + p1;
#pragma unroll
        for (int j = 0; j < 4; j++) {
            acc[j].x = fmaf(p0, va[j].x, fmaf(p1, vc[j].x, acc[j].x));
            acc[j].y = fmaf(p0, va[j].y, fmaf(p1, vc[j].y, acc[j].y));
            acc[j].z = fmaf(p0, va[j].z, fmaf(p1, vc[j].z, acc[j].z));
            acc[j].w = fmaf(p0, va[j].w, fmaf(p1, vc[j].w, acc[j].w));
        }
    }

    // -------- combine warps within block --------
    if (ln == 0) { s_m[w] = m; s_l[w] = l; }
    __syncthreads();
    const float M = fmaxf(fmaxf(s_m[0], s_m[1]), fmaxf(s_m[2], s_m[3]));
    const float scale = __expf(m - M);
#pragma unroll
    for (int j = 0; j < 4; j++) {
        const int d = 4 * (ln + 32 * j);
        atomicAdd(&s_acc[d + 0], scale * acc[j].x);
        atomicAdd(&s_acc[d + 1], scale * acc[j].y);
        atomicAdd(&s_acc[d + 2], scale * acc[j].z);
        atomicAdd(&s_acc[d + 3], scale * acc[j].w);
    }
    __syncthreads();

    const int pidx = blockIdx.x;
    if (threadIdx.x == 0) {
        float L = 0.f;
#pragma unroll
        for (int i = 0; i < NWARPS; i++) L += s_l[i] * __expf(s_m[i] - M);
        g_pm[pidx] = M;
        g_pl[pidx] = L;
    }
    for (int i = threadIdx.x; i < DD; i += NTHREADS)
        g_pacc[(size_t)pidx * DD + i] = s_acc[i];
}

__global__ __launch_bounds__(128)
void attn_part2(float* __restrict__ out)
{
    const int b = blockIdx.x;

    float M = -1e30f;
#pragma unroll
    for (int i = 0; i < NSPLIT; i++) M = fmaxf(M, g_pm[b * NSPLIT + i]);

    float wgt[NSPLIT];
    float L = 0.f;
#pragma unroll
    for (int i = 0; i < NSPLIT; i++) {
        wgt[i] = __expf(g_pm[b * NSPLIT + i] - M);
        L += g_pl[b * NSPLIT + i] * wgt[i];
    }
    const float invL = 1.0f / L;

    for (int d = threadIdx.x; d < DD; d += 128) {
        float a = 0.f;
#pragma unroll
        for (int i = 0; i < NSPLIT; i++)
            a += wgt[i] * g_pacc[(size_t)(b * NSPLIT + i) * DD + d];
        out[(size_t)b * DD + d] = a * invL;
    }
}

extern "C" void kernel_launch(void* const* d_in, const int* in_sizes, int n_in,
                              void* d_out, int out_size)
{
    const float* q    = (const float*)d_in[0];   // [32, 512]
    const float* k    = (const float*)d_in[1];   // [32, 8192, 512]
    const float* v    = (const float*)d_in[2];   // [32, 8192, 512]
    const int*   mask = (const int*)  d_in[3];   // [32, 1, 8192]
    float* out = (float*)d_out;                  // [32, 512]

    attn_part1<<<NBLK, NTHREADS>>>(q, k, v, mask);
    attn_part2<<<BB, 128>>>(out);
}

// round 5
// speedup vs baseline: 1.0144x; 1.0144x over previous
#include <cuda_runtime.h>

// Attention decode: out[b,:] = softmax(q[b]·K[b]^T masked) · V[b]
// B=32, S=8192, D=512, fp32. HBM-bound: ~1.07 GB/launch.
// Single fused kernel: split-K flash-decode + per-batch fan-in reduction.

#define BB      32
#define SS      8192
#define DD      512
#define NSPLIT  16
#define ROWS_PER_BLOCK (SS / NSPLIT)    // 512
#define NWARPS  4
#define NTHREADS (NWARPS * 32)          // 128
#define NBLK    (BB * NSPLIT)           // 512

// Split-K partials + fan-in counters (scratch; __device__ globals per rules)
__device__ float g_pm[NBLK];
__device__ float g_pl[NBLK];
__device__ float g_pacc[NBLK * DD];
__device__ int   g_cnt[BB] = {0};   // always returns to 0 by kernel end

__global__ __launch_bounds__(NTHREADS, 4)
void attn_fused(const float* __restrict__ q,
                const float* __restrict__ k,
                const float* __restrict__ v,
                const int*   __restrict__ mask,
                float* __restrict__ out)
{
    __shared__ float s_m[NWARPS];
    __shared__ float s_l[NWARPS];
    __shared__ float s_acc[DD];
    __shared__ int   s_last;

    const int b     = blockIdx.x / NSPLIT;
    const int split = blockIdx.x % NSPLIT;
    const int w     = threadIdx.x >> 5;
    const int ln    = threadIdx.x & 31;

    // zero shared accumulator
    for (int i = threadIdx.x; i < DD; i += NTHREADS) s_acc[i] = 0.0f;

    // q fragment: lane ln holds dims {4*(ln+32*j) + c}, j=0..3, c=0..3
    const float4* q4 = (const float4*)(q + (size_t)b * DD);
    float4 qf[4];
#pragma unroll
    for (int j = 0; j < 4; j++) qf[j] = q4[ln + 32 * j];

    const float4* kb = (const float4*)(k + (size_t)b * SS * DD);
    const float4* vb = (const float4*)(v + (size_t)b * SS * DD);
    const int*    mb = mask + (size_t)b * SS;

    float  m = -1e30f;
    float  l = 0.0f;
    float4 acc[4];
#pragma unroll
    for (int j = 0; j < 4; j++) acc[j] = make_float4(0.f, 0.f, 0.f, 0.f);

    const int row_base = split * ROWS_PER_BLOCK;

    // each warp handles row-pairs with warp stride
    for (int t = w; t < ROWS_PER_BLOCK / 2; t += NWARPS) {
        const int r0 = row_base + 2 * t;
        const int r1 = r0 + 1;
        const float4* k0 = kb + (size_t)r0 * (DD / 4);
        const float4* k1 = kb + (size_t)r1 * (DD / 4);
        const float4* v0 = vb + (size_t)r0 * (DD / 4);
        const float4* v1 = vb + (size_t)r1 * (DD / 4);

        // issue mask + all 16 streaming loads up front: 8 KB in flight per warp
        const int m0 = __ldg(&mb[r0]);
        const int m1 = __ldg(&mb[r1]);
        float4 ka[4], kc[4], va[4], vc[4];
#pragma unroll
        for (int j = 0; j < 4; j++) {
            ka[j] = __ldcs(&k0[ln + 32 * j]);
            kc[j] = __ldcs(&k1[ln + 32 * j]);
            va[j] = __ldcs(&v0[ln + 32 * j]);
            vc[j] = __ldcs(&v1[ln + 32 * j]);
        }

        float d0 = 0.f, d1 = 0.f;
#pragma unroll
        for (int j = 0; j < 4; j++) {
            d0 = fmaf(qf[j].x, ka[j].x, d0); d0 = fmaf(qf[j].y, ka[j].y, d0);
            d0 = fmaf(qf[j].z, ka[j].z, d0); d0 = fmaf(qf[j].w, ka[j].w, d0);
            d1 = fmaf(qf[j].x, kc[j].x, d1); d1 = fmaf(qf[j].y, kc[j].y, d1);
            d1 = fmaf(qf[j].z, kc[j].z, d1); d1 = fmaf(qf[j].w, kc[j].w, d1);
        }
        // warp butterfly reduce (all lanes end with the full dot)
#pragma unroll
        for (int o = 16; o > 0; o >>= 1) {
            d0 += __shfl_xor_sync(0xffffffffu, d0, o);
            d1 += __shfl_xor_sync(0xffffffffu, d1, o);
        }

        const float s0 = (m0 != 0) ? d0 : -1e9f;
        const float s1 = (m1 != 0) ? d1 : -1e9f;

        const float mn = fmaxf(m, fmaxf(s0, s1));
        if (mn > m) {  // warp-uniform, rare after warmup
            const float corr = __expf(m - mn);
            l *= corr;
#pragma unroll
            for (int j = 0; j < 4; j++) {
                acc[j].x *= corr; acc[j].y *= corr;
                acc[j].z *= corr; acc[j].w *= corr;
            }
            m = mn;
        }
        const float p0 = __expf(s0 - m);
        const float p1 = __expf(s1 - m);
        l += p0 + p1;
#pragma unroll
        for (int j = 0; j < 4; j++) {
            acc[j].x = fmaf(p0, va[j].x, fmaf(p1, vc[j].x, acc[j].x));
            acc[j].y = fmaf(p0, va[j].y, fmaf(p1, vc[j].y, acc[j].y));
            acc[j].z = fmaf(p0, va[j].z, fmaf(p1, vc[j].z, acc[j].z));
            acc[j].w = fmaf(p0, va[j].w, fmaf(p1, vc[j].w, acc[j].w));
        }
    }

    // -------- combine warps within block --------
    if (ln == 0) { s_m[w] = m; s_l[w] = l; }
    __syncthreads();
    const float M = fmaxf(fmaxf(s_m[0], s_m[1]), fmaxf(s_m[2], s_m[3]));
    const float scale = __expf(m - M);
#pragma unroll
    for (int j = 0; j < 4; j++) {
        const int d = 4 * (ln + 32 * j);
        atomicAdd(&s_acc[d + 0], scale * acc[j].x);
        atomicAdd(&s_acc[d + 1], scale * acc[j].y);
        atomicAdd(&s_acc[d + 2], scale * acc[j].z);
        atomicAdd(&s_acc[d + 3], scale * acc[j].w);
    }
    __syncthreads();

    // -------- write partials --------
    const int pidx = blockIdx.x;
    if (threadIdx.x == 0) {
        float L = 0.f;
#pragma unroll
        for (int i = 0; i < NWARPS; i++) L += s_l[i] * __expf(s_m[i] - M);
        g_pm[pidx] = M;
        g_pl[pidx] = L;
    }
    for (int i = threadIdx.x; i < DD; i += NTHREADS)
        g_pacc[(size_t)pidx * DD + i] = s_acc[i];

    // -------- fan-in: last CTA of this batch reduces the 16 splits --------
    __threadfence();
    __syncthreads();
    if (threadIdx.x == 0)
        s_last = (atomicAdd(&g_cnt[b], 1) == NSPLIT - 1) ? 1 : 0;
    __syncthreads();
    if (!s_last) return;

    // All 128 threads: redundant tiny reduction of (m,l) over 16 splits
    float Mg = -1e30f;
#pragma unroll
    for (int i = 0; i < NSPLIT; i++) Mg = fmaxf(Mg, g_pm[b * NSPLIT + i]);
    float wgt[NSPLIT];
    float Lg = 0.f;
#pragma unroll
    for (int i = 0; i < NSPLIT; i++) {
        wgt[i] = __expf(g_pm[b * NSPLIT + i] - Mg);
        Lg += g_pl[b * NSPLIT + i] * wgt[i];
    }
    const float invL = 1.0f / Lg;

    for (int d = threadIdx.x; d < DD; d += NTHREADS) {
        float a = 0.f;
#pragma unroll
        for (int i = 0; i < NSPLIT; i++)
            a += wgt[i] * g_pacc[(size_t)(b * NSPLIT + i) * DD + d];
        out[(size_t)b * DD + d] = a * invL;
    }

    // reset counter for next graph replay (deterministic: ends at 0)
    if (threadIdx.x == 0) g_cnt[b] = 0;
}

extern "C" void kernel_launch(void* const* d_in, const int* in_sizes, int n_in,
                              void* d_out, int out_size)
{
    const float* q    = (const float*)d_in[0];   // [32, 512]
    const float* k    = (const float*)d_in[1];   // [32, 8192, 512]
    const float* v    = (const float*)d_in[2];   // [32, 8192, 512]
    const int*   mask = (const int*)  d_in[3];   // [32, 1, 8192]
    float* out = (float*)d_out;                  // [32, 512]

    attn_fused<<<NBLK, NTHREADS>>>(q, k, v, mask, out);
}